// round 2
// baseline (speedup 1.0000x reference)
#include <cuda_runtime.h>
#include <math.h>

#define BB   128
#define NN   22
#define FF   448
#define HD   64
#define NPAIR 484
#define NUP   231   // i<j
#define NUPD  253   // i<=j
#define PSTR  65    // proj row stride (conflict-free: 65%32==1)
#define NPACK 11    // 22 rows -> 11 f32x2 pairs
#define KPAD  12    // padded pair count per k-slice

struct __align__(16) Smem {
    float2 xsp[FF * KPAD];        // packed x: [k][p] = (x[2p][k], x[2p+1][k])
    float  proj[4][NN * PSTR];    // u, v, p, q
    float  sw2s[HD * 36];         // sw2 rows padded to 36 (16B-aligned rows)
    float  embs[NN * HD];
    float  corrs[NPAIR], gcs[NPAIR], adjs[NPAIR];
    float  cw2s[HD], lngs[HD], lnbs[HD], sb2s[32], sw3s[32];
    float  mu[NN], istd[NN];
    int    pl[NUP], plg[NUPD];
};

__device__ __forceinline__ void fma2(float2& d, const float2 a, const float2 b) {
    asm("fma.rn.f32x2 %0, %1, %2, %0;"
        : "+l"(*reinterpret_cast<unsigned long long*>(&d))
        : "l"(*reinterpret_cast<const unsigned long long*>(&a)),
          "l"(*reinterpret_cast<const unsigned long long*>(&b)));
}

__device__ __forceinline__ float warpSum(float v) {
    #pragma unroll
    for (int o = 16; o; o >>= 1) v += __shfl_xor_sync(0xffffffffu, v, o);
    return v;
}

__global__ __launch_bounds__(512, 1)
void fused_kernel(const float* __restrict__ x,
                  const float* __restrict__ cw1, const float* __restrict__ cb1,
                  const float* __restrict__ cw2, const float* __restrict__ cb2,
                  const float* __restrict__ emb,
                  const float* __restrict__ sw1, const float* __restrict__ sb1,
                  const float* __restrict__ lng, const float* __restrict__ lnb,
                  const float* __restrict__ sw2, const float* __restrict__ sb2,
                  const float* __restrict__ sw3, const float* __restrict__ sb3,
                  const float* __restrict__ thr, const float* __restrict__ alpha_p,
                  float* __restrict__ out) {
    extern __shared__ __align__(16) char smem_raw[];
    Smem* s = reinterpret_cast<Smem*>(smem_raw);

    const int b    = blockIdx.x;
    const int tid  = threadIdx.x;
    const int warp = tid >> 5;
    const int lane = tid & 31;
    float* xw = reinterpret_cast<float*>(s->xsp);  // word view of packed x

    // ---------------- Phase 1: cooperative loads ----------------
    {
        const float* xb = x + (size_t)b * NN * FF;
        for (int idx = tid; idx < NN * FF; idx += 512) {
            int i = idx / FF, k = idx - i * FF;
            xw[k * (2 * KPAD) + (i >> 1) * 2 + (i & 1)] = xb[idx];
        }
        for (int idx = tid; idx < HD * 32; idx += 512) {
            int c = idx >> 5, o = idx & 31;
            s->sw2s[c * 36 + o] = sw2[idx];
        }
        for (int idx = tid; idx < NN * HD; idx += 512) s->embs[idx] = emb[idx];
        for (int idx = tid; idx < NPAIR; idx += 512) s->adjs[idx] = 0.f;
        if (tid < HD) { s->cw2s[tid] = cw2[tid]; s->lngs[tid] = lng[tid]; s->lnbs[tid] = lnb[tid]; }
        if (tid >= HD && tid < HD + 32) { s->sb2s[tid - HD] = sb2[tid - HD]; s->sw3s[tid - HD] = sw3[tid - HD]; }
        if (tid < NPAIR) {
            int i = tid / NN, j = tid - i * NN;
            if (i < j)  s->pl [i * (2 * NN - 1 - i) / 2 + (j - i - 1)] = (i << 5) | j;
            if (i <= j) s->plg[i * (2 * NN + 1 - i) / 2 + (j - i)]     = (i << 5) | j;
        }
    }
    __syncthreads();

    // ---------------- Phase 2: per-row stats (warp per row) ----------------
    for (int i = warp; i < NN; i += 16) {
        const int oi = (i >> 1) * 2 + (i & 1);
        float sm = 0.f, sq = 0.f;
        for (int k = lane; k < FF; k += 32) {
            float v = xw[k * (2 * KPAD) + oi];
            sm += v; sq += v * v;
        }
        sm = warpSum(sm); sq = warpSum(sq);
        if (lane == 0) {
            float m = sm / FF;
            float var = (sq - FF * m * m) / (FF - 1);
            var = fmaxf(var, 0.f);
            s->mu[i] = m;
            s->istd[i] = 1.0f / (sqrtf(var) + 1e-8f);
        }
    }

    // ---------------- Phase 3: projections via FFMA2 ----------------
    // tid -> m (matrix 0..3), c32 (col pair base), ks (k-split 0..3)
    {
        const int m   = tid >> 7;
        const int c32 = (tid >> 2) & 31;
        const int ks  = tid & 3;
        const float* Wb;
        if      (m == 0) Wb = cw1;
        else if (m == 1) Wb = cw1 + 448 * HD;
        else if (m == 2) Wb = sw1 + 128 * HD;
        else             Wb = sw1 + 576 * HD;

        float2 acc[2 * NPACK];
        #pragma unroll
        for (int p = 0; p < 2 * NPACK; p++) acc[p] = make_float2(0.f, 0.f);

        const int k0 = ks * (FF / 4);
        #pragma unroll 2
        for (int k = k0; k < k0 + FF / 4; k++) {
            float w0 = Wb[k * HD + c32];
            float w1 = Wb[k * HD + c32 + 32];
            float2 wd0 = make_float2(w0, w0);
            float2 wd1 = make_float2(w1, w1);
            const float2* xk = s->xsp + k * KPAD;
            #pragma unroll
            for (int p = 0; p < NPACK; p++) {
                float2 xv = xk[p];
                fma2(acc[p],         xv, wd0);
                fma2(acc[p + NPACK], xv, wd1);
            }
        }
        // reduce across ks (lanes xor 1,2)
        #pragma unroll
        for (int r = 1; r <= 2; r <<= 1)
            #pragma unroll
            for (int p = 0; p < 2 * NPACK; p++) {
                acc[p].x += __shfl_xor_sync(0xffffffffu, acc[p].x, r);
                acc[p].y += __shfl_xor_sync(0xffffffffu, acc[p].y, r);
            }
        if (ks == 0) {
            float b0 = (m == 0) ? cb1[c32]      : 0.f;
            float b1 = (m == 0) ? cb1[c32 + 32] : 0.f;
            float* pm = s->proj[m];
            #pragma unroll
            for (int p = 0; p < NPACK; p++) {
                pm[(2 * p)     * PSTR + c32]      = acc[p].x + b0;
                pm[(2 * p + 1) * PSTR + c32]      = acc[p].y + b0;
                pm[(2 * p)     * PSTR + c32 + 32] = acc[p + NPACK].x + b1;
                pm[(2 * p + 1) * PSTR + c32 + 32] = acc[p + NPACK].y + b1;
            }
        }
    }
    __syncthreads();

    // ---------------- Phase 4: gram/corr (threads <253) || emb-proj fold (threads >=256) ----------------
    if (tid < NUPD) {
        int code = s->plg[tid];
        int i = code >> 5, j = code & 31;
        const int oi = (i >> 1) * 2 + (i & 1);
        const int oj = (j >> 1) * 2 + (j & 1);
        float dot = 0.f;
        #pragma unroll 4
        for (int k = 0; k < FF; k++)
            dot += xw[k * (2 * KPAD) + oi] * xw[k * (2 * KPAD) + oj];
        float cv = fabsf((dot - (float)FF * s->mu[i] * s->mu[j]) * s->istd[i] * s->istd[j]) * (1.0f / FF);
        s->corrs[i * NN + j] = cv;
        s->corrs[j * NN + i] = cv;
    } else if (tid >= 256) {
        const int t = tid - 256;
        for (int o = t; o < 2 * NN * HD; o += 256) {
            int half = (o >= NN * HD) ? 1 : 0;
            int r = o - half * NN * HD;
            int i = r >> 6, c = r & 63;
            const float* W = sw1 + half * HD * HD + c;
            const float* e = s->embs + i * HD;
            float acc = half ? 0.f : sb1[c];
            #pragma unroll 8
            for (int kk = 0; kk < HD; kk++) acc += e[kk] * W[kk * HD];
            s->proj[2 + half][i * PSTR + c] += acc;
        }
    }
    __syncthreads();

    // ---------------- Phase 5: semantic MLP (threads <231) || corr MLP (threads >=256) ----------------
    if (tid < NUP) {
        const float tthr = 1.0f / (1.0f + __expf(-thr[0]));
        int code = s->pl[tid];
        int i = code >> 5, j = code & 31;
        const float* pi = s->proj[2] + i * PSTR;
        const float* qj = s->proj[3] + j * PSTR;
        // pass A: mean / var
        float sm = 0.f, sq = 0.f;
        #pragma unroll 4
        for (int c = 0; c < HD; c++) {
            float sv = pi[c] + qj[c];
            sm += sv; sq += sv * sv;
        }
        float muv  = sm * (1.0f / HD);
        float var  = sq * (1.0f / HD) - muv * muv;
        float rstd = rsqrtf(var + 1e-5f);
        // pass B: h1 -> h2 (f32x2 matvec)
        float2 h2p[16];
        #pragma unroll
        for (int o = 0; o < 16; o++) h2p[o] = make_float2(s->sb2s[2 * o], s->sb2s[2 * o + 1]);
        #pragma unroll 2
        for (int c = 0; c < HD; c++) {
            float sv = pi[c] + qj[c];
            float h1 = fmaxf((sv - muv) * rstd * s->lngs[c] + s->lnbs[c], 0.f);
            float2 h1d = make_float2(h1, h1);
            const float4* wr = reinterpret_cast<const float4*>(s->sw2s + c * 36);
            #pragma unroll
            for (int o4 = 0; o4 < 8; o4++) {
                float4 w = wr[o4];
                fma2(h2p[2 * o4],     h1d, make_float2(w.x, w.y));
                fma2(h2p[2 * o4 + 1], h1d, make_float2(w.z, w.w));
            }
        }
        float z = sb3[0];
        #pragma unroll
        for (int o = 0; o < 16; o++) {
            z += fmaxf(h2p[o].x, 0.f) * s->sw3s[2 * o];
            z += fmaxf(h2p[o].y, 0.f) * s->sw3s[2 * o + 1];
        }
        float ws  = 1.0f / (1.0f + __expf(-z));
        float val = (ws > tthr) ? ws : 0.f;
        s->adjs[i * NN + j] = val;
        s->adjs[j * NN + i] = val;
    } else if (tid >= 256) {
        const float cb2v = cb2[0];
        const int t = tid - 256;
        for (int pidx = t; pidx < NPAIR; pidx += 256) {
            int i = pidx / NN, j = pidx - i * NN;
            const float* ui = s->proj[0] + i * PSTR;
            const float* vj = s->proj[1] + j * PSTR;
            float z = cb2v;
            #pragma unroll 4
            for (int c = 0; c < HD; c++)
                z += fmaxf(ui[c] + vj[c], 0.f) * s->cw2s[c];
            float wc = 1.0f / (1.0f + __expf(-z));
            s->gcs[pidx] = s->corrs[pidx] * wc;
        }
    }
    __syncthreads();

    // ---------------- Phase 6: fuse + store ----------------
    if (tid < NPAIR) {
        const float alpha = 1.0f / (1.0f + __expf(-alpha_p[0]));
        int i = tid / NN, j = tid - i * NN;
        float eye = (i == j) ? 1.0f : 0.0f;
        out[(size_t)b * NPAIR + tid] = alpha * s->gcs[tid] + (1.0f - alpha) * s->adjs[tid] + eye;
    }
}

extern "C" void kernel_launch(void* const* d_in, const int* in_sizes, int n_in,
                              void* d_out, int out_size) {
    const float* x       = (const float*)d_in[0];
    const float* cw1     = (const float*)d_in[1];
    const float* cb1     = (const float*)d_in[2];
    const float* cw2     = (const float*)d_in[3];
    const float* cb2     = (const float*)d_in[4];
    const float* emb     = (const float*)d_in[5];
    const float* sw1     = (const float*)d_in[6];
    const float* sb1     = (const float*)d_in[7];
    const float* ln_g    = (const float*)d_in[8];
    const float* ln_b    = (const float*)d_in[9];
    const float* sw2     = (const float*)d_in[10];
    const float* sb2     = (const float*)d_in[11];
    const float* sw3     = (const float*)d_in[12];
    const float* sb3     = (const float*)d_in[13];
    const float* thr     = (const float*)d_in[14];
    const float* alpha_p = (const float*)d_in[15];
    float* out = (float*)d_out;

    static bool attr_set = false;
    if (!attr_set) {
        cudaFuncSetAttribute(fused_kernel, cudaFuncAttributeMaxDynamicSharedMemorySize,
                             (int)sizeof(Smem));
        attr_set = true;
    }
    fused_kernel<<<BB, 512, sizeof(Smem)>>>(x, cw1, cb1, cw2, cb2, emb, sw1, sb1,
                                            ln_g, ln_b, sw2, sb2, sw3, sb3, thr, alpha_p, out);
}

// round 3
// speedup vs baseline: 2.7130x; 2.7130x over previous
#include <cuda_runtime.h>
#include <math.h>

#define BB    128
#define NN    22
#define FF    448
#define HD    64
#define NPAIR 484
#define NUP   231      // i<j
#define NUPD  253      // i<=j
#define PSTR  65       // proj row stride (floats)
#define XSS   452      // xs row stride (floats), 16B-aligned rows
#define XQF   1032     // xq row stride in floats (= 516 float2)
#define KV    512      // virtual K: 64 emb + 448 x

struct __align__(16) Smem {
    float xq[12 * XQF];          // packed pairs: [p][kk] -> (row2p[kk], row2p+1[kk]); kk<64 emb, >=64 x
    float xs[NN * XSS];          // row-major x copy
    float proj[4][NN * PSTR];    // u, v, p, q
    float sw2s[HD * 36];
    float corrs[NPAIR], gcs[NPAIR], adjs[NPAIR];
    float cw2s[HD], lngs[HD], lnbs[HD], sb2s[32], sw3s[32];
    float mu[NN], istd[NN];
    int   pl[NUP], plg[NUPD];
};

__device__ __forceinline__ void fma2b(float2& d, float x0, float x1, float w) {
    float2 a = make_float2(x0, x1);
    float2 b = make_float2(w, w);
    asm("fma.rn.f32x2 %0, %1, %2, %0;"
        : "+l"(*reinterpret_cast<unsigned long long*>(&d))
        : "l"(*reinterpret_cast<const unsigned long long*>(&a)),
          "l"(*reinterpret_cast<const unsigned long long*>(&b)));
}

__device__ __forceinline__ void fma2(float2& d, const float2 a, const float2 b) {
    asm("fma.rn.f32x2 %0, %1, %2, %0;"
        : "+l"(*reinterpret_cast<unsigned long long*>(&d))
        : "l"(*reinterpret_cast<const unsigned long long*>(&a)),
          "l"(*reinterpret_cast<const unsigned long long*>(&b)));
}

__device__ __forceinline__ float warpSum(float v) {
    #pragma unroll
    for (int o = 16; o; o >>= 1) v += __shfl_xor_sync(0xffffffffu, v, o);
    return v;
}

// one GEMM micro-step: pair-acc A[4], x float4 (2 k's for this row-pair), weights w0/w1 (4 cols, k and k+1)
#define PSTEP(A, XV)                                          \
    fma2b(A[0], XV.x, XV.y, w0.x); fma2b(A[0], XV.z, XV.w, w1.x); \
    fma2b(A[1], XV.x, XV.y, w0.y); fma2b(A[1], XV.z, XV.w, w1.y); \
    fma2b(A[2], XV.x, XV.y, w0.z); fma2b(A[2], XV.z, XV.w, w1.z); \
    fma2b(A[3], XV.x, XV.y, w0.w); fma2b(A[3], XV.z, XV.w, w1.w);

__global__ __launch_bounds__(512, 1)
void fused_kernel(const float* __restrict__ x,
                  const float* __restrict__ cw1, const float* __restrict__ cb1,
                  const float* __restrict__ cw2, const float* __restrict__ cb2,
                  const float* __restrict__ emb,
                  const float* __restrict__ sw1, const float* __restrict__ sb1,
                  const float* __restrict__ lng, const float* __restrict__ lnb,
                  const float* __restrict__ sw2, const float* __restrict__ sb2,
                  const float* __restrict__ sw3, const float* __restrict__ sb3,
                  const float* __restrict__ thr, const float* __restrict__ alpha_p,
                  float* __restrict__ out) {
    extern __shared__ __align__(16) char smem_raw[];
    Smem* s = reinterpret_cast<Smem*>(smem_raw);

    const int b    = blockIdx.x;
    const int tid  = threadIdx.x;
    const int warp = tid >> 5;
    const int lane = tid & 31;

    // ---------------- Phase 1: load + layout ----------------
    {
        const float* xb = x + (size_t)b * NN * FF;
        for (int idx = tid; idx < NN * FF; idx += 512) {
            int i = idx / FF, k = idx - i * FF;
            float v = xb[idx];
            s->xs[i * XSS + k] = v;
            s->xq[(i >> 1) * XQF + (64 + k) * 2 + (i & 1)] = v;
        }
        for (int idx = tid; idx < NN * HD; idx += 512) {
            int i = idx >> 6, k = idx & 63;
            s->xq[(i >> 1) * XQF + k * 2 + (i & 1)] = emb[idx];
        }
        for (int idx = tid; idx < XQF; idx += 512) s->xq[11 * XQF + idx] = 0.f;  // pad pair
        for (int idx = tid; idx < HD * 32; idx += 512) {
            int c = idx >> 5, o = idx & 31;
            s->sw2s[c * 36 + o] = sw2[idx];
        }
        for (int idx = tid; idx < NPAIR; idx += 512) s->adjs[idx] = 0.f;
        if (tid < HD) { s->cw2s[tid] = cw2[tid]; s->lngs[tid] = lng[tid]; s->lnbs[tid] = lnb[tid]; }
        if (tid >= HD && tid < HD + 32) { s->sb2s[tid - HD] = sb2[tid - HD]; s->sw3s[tid - HD] = sw3[tid - HD]; }
        if (tid < NPAIR) {
            int i = tid / NN, j = tid - i * NN;
            if (i < j)  s->pl [i * (2 * NN - 1 - i) / 2 + (j - i - 1)] = (i << 5) | j;
            if (i <= j) s->plg[i * (2 * NN + 1 - i) / 2 + (j - i)]     = (i << 5) | j;
        }
    }
    __syncthreads();

    // ---------------- Phase 2: per-row stats (warp per row, float4) ----------------
    for (int i = warp; i < NN; i += 16) {
        float sm = 0.f, sq = 0.f;
        const float* r = s->xs + i * XSS;
        for (int k = lane * 4; k < FF; k += 128) {
            float4 v = *reinterpret_cast<const float4*>(r + k);
            sm += v.x + v.y + v.z + v.w;
            sq += v.x * v.x + v.y * v.y + v.z * v.z + v.w * v.w;
        }
        sm = warpSum(sm); sq = warpSum(sq);
        if (lane == 0) {
            float m = sm / FF;
            float var = (sq - FF * m * m) / (FF - 1);
            var = fmaxf(var, 0.f);
            s->mu[i] = m;
            s->istd[i] = 1.0f / (sqrtf(var) + 1e-8f);
        }
    }

    // ---------------- Phase 3: projection GEMM (FFMA2, 4 cols x 3 pairs) ----------------
    // tid bits: [0:3]=c4, [4]=ks, [5:6]=rg, [7:8]=m  (warp-uniform rg,m; lanes = c4 x ks)
    {
        const int m  = tid >> 7;
        const int ks = (tid >> 4) & 1;
        const int c0 = (tid & 15) * 4;
        const int rg = (tid >> 5) & 3;
        const int p0 = rg * 3;

        float2 acc[3][4];
        #pragma unroll
        for (int pp = 0; pp < 3; pp++)
            #pragma unroll
            for (int cc = 0; cc < 4; cc++) acc[pp][cc] = make_float2(0.f, 0.f);

        // segment B: x part (448 rows), split by ks (224 each)
        const float* wB;
        if      (m == 0) wB = cw1 + (       ks * 224) * HD + c0;
        else if (m == 1) wB = cw1 + (448  + ks * 224) * HD + c0;
        else if (m == 2) wB = sw1 + (128  + ks * 224) * HD + c0;
        else             wB = sw1 + (576  + ks * 224) * HD + c0;

        const float4* xr0 = reinterpret_cast<const float4*>(s->xq + (p0 + 0) * XQF + (64 + ks * 224) * 2);
        const float4* xr1 = reinterpret_cast<const float4*>(s->xq + (p0 + 1) * XQF + (64 + ks * 224) * 2);
        const float4* xr2 = reinterpret_cast<const float4*>(s->xq + (p0 + 2) * XQF + (64 + ks * 224) * 2);

        #pragma unroll 4
        for (int it = 0; it < 112; it++) {
            float4 w0 = *reinterpret_cast<const float4*>(wB);
            float4 w1 = *reinterpret_cast<const float4*>(wB + HD);
            wB += 2 * HD;
            float4 xa = xr0[it];
            float4 xb4 = xr1[it];
            float4 xc = xr2[it];
            PSTEP(acc[0], xa);
            PSTEP(acc[1], xb4);
            PSTEP(acc[2], xc);
        }

        // segment A: emb part (64 rows), m>=2 only (warp-uniform branch)
        if (m >= 2) {
            const float* wA = sw1 + ((m == 3 ? 64 : 0) + ks * 32) * HD + c0;
            const float4* ar0 = reinterpret_cast<const float4*>(s->xq + (p0 + 0) * XQF + (ks * 32) * 2);
            const float4* ar1 = reinterpret_cast<const float4*>(s->xq + (p0 + 1) * XQF + (ks * 32) * 2);
            const float4* ar2 = reinterpret_cast<const float4*>(s->xq + (p0 + 2) * XQF + (ks * 32) * 2);
            #pragma unroll 4
            for (int it = 0; it < 16; it++) {
                float4 w0 = *reinterpret_cast<const float4*>(wA);
                float4 w1 = *reinterpret_cast<const float4*>(wA + HD);
                wA += 2 * HD;
                float4 xa = ar0[it];
                float4 xb4 = ar1[it];
                float4 xc = ar2[it];
                PSTEP(acc[0], xa);
                PSTEP(acc[1], xb4);
                PSTEP(acc[2], xc);
            }
        }

        // reduce ks halves (lanes xor 16)
        #pragma unroll
        for (int pp = 0; pp < 3; pp++)
            #pragma unroll
            for (int cc = 0; cc < 4; cc++) {
                unsigned long long v = *reinterpret_cast<unsigned long long*>(&acc[pp][cc]);
                unsigned long long o = __shfl_xor_sync(0xffffffffu, v, 16);
                float2 ov = *reinterpret_cast<float2*>(&o);
                acc[pp][cc].x += ov.x;
                acc[pp][cc].y += ov.y;
            }

        if (ks == 0) {
            float4 bb = make_float4(0.f, 0.f, 0.f, 0.f);
            if (m == 0) bb = *reinterpret_cast<const float4*>(cb1 + c0);
            if (m == 2) bb = *reinterpret_cast<const float4*>(sb1 + c0);
            float bcol[4] = {bb.x, bb.y, bb.z, bb.w};
            const int npp = (rg == 3) ? 2 : 3;
            float* pm = s->proj[m];
            #pragma unroll
            for (int pp = 0; pp < 3; pp++) {
                if (pp < npp) {
                    int r0 = (p0 + pp) * 2;
                    #pragma unroll
                    for (int cc = 0; cc < 4; cc++) {
                        pm[r0 * PSTR + c0 + cc]       = acc[pp][cc].x + bcol[cc];
                        pm[(r0 + 1) * PSTR + c0 + cc] = acc[pp][cc].y + bcol[cc];
                    }
                }
            }
        }
    }
    __syncthreads();

    // ---------------- Phase 4: gram/corr (warp per pair, float4) ----------------
    for (int pi = warp; pi < NUPD; pi += 16) {
        int code = s->plg[pi];
        int i = code >> 5, j = code & 31;
        const float* ri = s->xs + i * XSS;
        const float* rj = s->xs + j * XSS;
        float dot = 0.f;
        for (int k = lane * 4; k < FF; k += 128) {
            float4 a = *reinterpret_cast<const float4*>(ri + k);
            float4 c = *reinterpret_cast<const float4*>(rj + k);
            dot += a.x * c.x + a.y * c.y + a.z * c.z + a.w * c.w;
        }
        dot = warpSum(dot);
        if (lane == 0) {
            float cv = fabsf((dot - (float)FF * s->mu[i] * s->mu[j]) * s->istd[i] * s->istd[j]) * (1.0f / FF);
            s->corrs[i * NN + j] = cv;
            s->corrs[j * NN + i] = cv;
        }
    }
    __syncthreads();

    // ---------------- Phase 5: semantic MLP (tid<231) || corr MLP (tid>=256) ----------------
    if (tid < NUP) {
        const float tthr = 1.0f / (1.0f + __expf(-thr[0]));
        int code = s->pl[tid];
        int i = code >> 5, j = code & 31;
        const float* pi = s->proj[2] + i * PSTR;
        const float* qj = s->proj[3] + j * PSTR;
        float sm = 0.f, sq = 0.f;
        #pragma unroll 4
        for (int c = 0; c < HD; c++) {
            float sv = pi[c] + qj[c];
            sm += sv; sq += sv * sv;
        }
        float muv  = sm * (1.0f / HD);
        float var  = sq * (1.0f / HD) - muv * muv;
        float rstd = rsqrtf(var + 1e-5f);
        float2 h2p[16];
        #pragma unroll
        for (int o = 0; o < 16; o++) h2p[o] = make_float2(s->sb2s[2 * o], s->sb2s[2 * o + 1]);
        #pragma unroll 2
        for (int c = 0; c < HD; c++) {
            float sv = pi[c] + qj[c];
            float h1 = fmaxf((sv - muv) * rstd * s->lngs[c] + s->lnbs[c], 0.f);
            float2 h1d = make_float2(h1, h1);
            const float4* wr = reinterpret_cast<const float4*>(s->sw2s + c * 36);
            #pragma unroll
            for (int o4 = 0; o4 < 8; o4++) {
                float4 w = wr[o4];
                fma2(h2p[2 * o4],     h1d, make_float2(w.x, w.y));
                fma2(h2p[2 * o4 + 1], h1d, make_float2(w.z, w.w));
            }
        }
        float z = sb3[0];
        #pragma unroll
        for (int o = 0; o < 16; o++) {
            z += fmaxf(h2p[o].x, 0.f) * s->sw3s[2 * o];
            z += fmaxf(h2p[o].y, 0.f) * s->sw3s[2 * o + 1];
        }
        float ws  = 1.0f / (1.0f + __expf(-z));
        float val = (ws > tthr) ? ws : 0.f;
        s->adjs[i * NN + j] = val;
        s->adjs[j * NN + i] = val;
    } else if (tid >= 256) {
        const float cb2v = cb2[0];
        for (int pidx = tid - 256; pidx < NPAIR; pidx += 256) {
            int i = pidx / NN, j = pidx - i * NN;
            const float* ui = s->proj[0] + i * PSTR;
            const float* vj = s->proj[1] + j * PSTR;
            float z = cb2v;
            #pragma unroll 4
            for (int c = 0; c < HD; c++)
                z += fmaxf(ui[c] + vj[c], 0.f) * s->cw2s[c];
            float wc = 1.0f / (1.0f + __expf(-z));
            s->gcs[pidx] = s->corrs[pidx] * wc;
        }
    }
    __syncthreads();

    // ---------------- Phase 6: fuse + store ----------------
    if (tid < NPAIR) {
        const float alpha = 1.0f / (1.0f + __expf(-alpha_p[0]));
        int i = tid / NN, j = tid - i * NN;
        float eye = (i == j) ? 1.0f : 0.0f;
        out[(size_t)b * NPAIR + tid] = alpha * s->gcs[tid] + (1.0f - alpha) * s->adjs[tid] + eye;
    }
}

extern "C" void kernel_launch(void* const* d_in, const int* in_sizes, int n_in,
                              void* d_out, int out_size) {
    const float* x       = (const float*)d_in[0];
    const float* cw1     = (const float*)d_in[1];
    const float* cb1     = (const float*)d_in[2];
    const float* cw2     = (const float*)d_in[3];
    const float* cb2     = (const float*)d_in[4];
    const float* emb     = (const float*)d_in[5];
    const float* sw1     = (const float*)d_in[6];
    const float* sb1     = (const float*)d_in[7];
    const float* ln_g    = (const float*)d_in[8];
    const float* ln_b    = (const float*)d_in[9];
    const float* sw2     = (const float*)d_in[10];
    const float* sb2     = (const float*)d_in[11];
    const float* sw3     = (const float*)d_in[12];
    const float* sb3     = (const float*)d_in[13];
    const float* thr     = (const float*)d_in[14];
    const float* alpha_p = (const float*)d_in[15];
    float* out = (float*)d_out;

    static bool attr_set = false;
    if (!attr_set) {
        cudaFuncSetAttribute(fused_kernel, cudaFuncAttributeMaxDynamicSharedMemorySize,
                             (int)sizeof(Smem));
        attr_set = true;
    }
    fused_kernel<<<BB, 512, sizeof(Smem)>>>(x, cw1, cb1, cw2, cb2, emb, sw1, sb1,
                                            ln_g, ln_b, sw2, sb2, sw3, sb3, thr, alpha_p, out);
}